// round 5
// baseline (speedup 1.0000x reference)
#include <cuda_runtime.h>
#include <cuda_bf16.h>
#include <cstdint>
#include <math.h>

#define T_TOK 4096
#define H_DIM 1024
#define F_DIM 2048
#define E_NUM 8
#define F2    (2 * F_DIM)

// ===================== helpers =====================
__device__ __forceinline__ uint32_t smem_u32(const void* p) {
    uint32_t a;
    asm("{ .reg .u64 t; cvta.to.shared.u64 t, %1; cvt.u32.u64 %0, t; }" : "=r"(a) : "l"(p));
    return a;
}
#define SW128(off) ((off) ^ (((off) >> 3) & 0x70))

__device__ __forceinline__ void cp_async16(uint32_t dst, const void* src, int srcBytes) {
    asm volatile("cp.async.cg.shared.global [%0], [%1], 16, %2;"
                 :: "r"(dst), "l"(src), "r"(srcBytes) : "memory");
}
#define CP_COMMIT() asm volatile("cp.async.commit_group;" ::: "memory")
#define CP_WAIT(n)  asm volatile("cp.async.wait_group %0;" :: "n"(n) : "memory")

__device__ __forceinline__ void ldsm4(uint32_t* r, uint32_t addr) {
    asm volatile("ldmatrix.sync.aligned.m8n8.x4.shared.b16 {%0,%1,%2,%3}, [%4];"
                 : "=r"(r[0]), "=r"(r[1]), "=r"(r[2]), "=r"(r[3]) : "r"(addr));
}

__device__ __forceinline__ void mma16816(float* d, const uint32_t* a, uint32_t b0, uint32_t b1) {
    asm volatile("mma.sync.aligned.m16n8k16.row.col.f32.bf16.bf16.f32 "
                 "{%0,%1,%2,%3}, {%4,%5,%6,%7}, {%8,%9}, {%0,%1,%2,%3};"
                 : "+f"(d[0]), "+f"(d[1]), "+f"(d[2]), "+f"(d[3])
                 : "r"(a[0]), "r"(a[1]), "r"(a[2]), "r"(a[3]), "r"(b0), "r"(b1));
}

__device__ __forceinline__ uint32_t pack_bf16(float x, float y) {
    __nv_bfloat162 t;
    t.x = __float2bfloat16(x);
    t.y = __float2bfloat16(y);
    return *(uint32_t*)&t;
}

// ===================== scratch (device globals; no allocs) =====================
__device__ __nv_bfloat16 g_x_hi [(size_t)T_TOK * H_DIM];
__device__ __nv_bfloat16 g_x_lo [(size_t)T_TOK * H_DIM];
__device__ __nv_bfloat16 g_sw1t_hi[(size_t)2 * F_DIM * H_DIM];
__device__ __nv_bfloat16 g_sw1t_lo[(size_t)2 * F_DIM * H_DIM];
__device__ __nv_bfloat16 g_ew1t_hi[(size_t)E_NUM * F_DIM * H_DIM];
__device__ __nv_bfloat16 g_ew1t_lo[(size_t)E_NUM * F_DIM * H_DIM];
__device__ __nv_bfloat16 g_sw2t_hi[(size_t)H_DIM * F2];
__device__ __nv_bfloat16 g_sw2t_lo[(size_t)H_DIM * F2];
__device__ __nv_bfloat16 g_ew2t_hi[(size_t)E_NUM * H_DIM * F_DIM];
__device__ __nv_bfloat16 g_ew2t_lo[(size_t)E_NUM * H_DIM * F_DIM];
__device__ __nv_bfloat16 g_hids_hi[(size_t)T_TOK * F2];
__device__ __nv_bfloat16 g_hids_lo[(size_t)T_TOK * F2];
__device__ __nv_bfloat16 g_hidr_hi[(size_t)2 * T_TOK * F_DIM];
__device__ __nv_bfloat16 g_hidr_lo[(size_t)2 * T_TOK * F_DIM];
__device__ float g_rout[(size_t)2 * T_TOK * H_DIM];
__device__ int g_counts[E_NUM];
__device__ int g_base[E_NUM];
__device__ int g_list[E_NUM * T_TOK];
__device__ int g_tok_e[2 * T_TOK];
__device__ int g_tok_slot[2 * T_TOK];

// ===================== small kernels =====================
__global__ void zero_kernel() {
    if (threadIdx.x < E_NUM) g_counts[threadIdx.x] = 0;
}

__global__ void router_kernel(const float* __restrict__ x,
                              const float* __restrict__ rw,
                              const float* __restrict__ rb) {
    int warp = (blockIdx.x * blockDim.x + threadIdx.x) >> 5;
    int lane = threadIdx.x & 31;
    if (warp >= T_TOK) return;
    const float* xp = x + (long)warp * H_DIM;
    float acc[E_NUM];
#pragma unroll
    for (int e = 0; e < E_NUM; e++) acc[e] = 0.f;
    for (int h = lane; h < H_DIM; h += 32) {
        float xv = xp[h];
        const float* w = rw + (long)h * E_NUM;
#pragma unroll
        for (int e = 0; e < E_NUM; e++) acc[e] = fmaf(xv, w[e], acc[e]);
    }
#pragma unroll
    for (int e = 0; e < E_NUM; e++)
#pragma unroll
        for (int off = 16; off; off >>= 1)
            acc[e] += __shfl_xor_sync(0xFFFFFFFFu, acc[e], off);
    if (lane == 0) {
        float lg[E_NUM];
#pragma unroll
        for (int e = 0; e < E_NUM; e++) lg[e] = acc[e] + rb[e];
        int e0 = 0;
#pragma unroll
        for (int e = 1; e < E_NUM; e++) if (lg[e] > lg[e0]) e0 = e;
        int e1 = -1;
#pragma unroll
        for (int e = 0; e < E_NUM; e++) {
            if (e == e0) continue;
            if (e1 < 0 || lg[e] > lg[e1]) e1 = e;
        }
        int sel[2] = { e0, e1 };
        int t = warp;
#pragma unroll
        for (int k = 0; k < 2; k++) {
            int e = sel[k];
            int slot = atomicAdd(&g_counts[e], 1);
            g_list[e * T_TOK + slot] = t;
            g_tok_e[2 * t + k] = e;
            g_tok_slot[2 * t + k] = slot;
        }
    }
}

__global__ void base_kernel() {
    if (threadIdx.x == 0) {
        int s = 0;
#pragma unroll
        for (int e = 0; e < E_NUM; e++) { g_base[e] = s; s += g_counts[e]; }
    }
}

__global__ void combine_kernel(float* __restrict__ out) {
    int t = blockIdx.x;
    int e0 = g_tok_e[2 * t], e1 = g_tok_e[2 * t + 1];
    long r0 = (long)g_base[e0] + g_tok_slot[2 * t];
    long r1 = (long)g_base[e1] + g_tok_slot[2 * t + 1];
    const float4* p0 = (const float4*)g_rout + r0 * (H_DIM / 4);
    const float4* p1 = (const float4*)g_rout + r1 * (H_DIM / 4);
    float4* op = (float4*)out + (long)t * (H_DIM / 4);
    int i = threadIdx.x;
    float4 o = op[i], a = p0[i], b = p1[i];
    o.x += a.x + b.x; o.y += a.y + b.y; o.z += a.z + b.z; o.w += a.w + b.w;
    op[i] = o;
}

// ===================== fp32 -> bf16 hi/lo converters =====================
__global__ void split_kernel(const float* __restrict__ in,
                             __nv_bfloat16* __restrict__ hi,
                             __nv_bfloat16* __restrict__ lo, int n4) {
    int i = blockIdx.x * blockDim.x + threadIdx.x;
    if (i >= n4) return;
    float4 v = ((const float4*)in)[i];
    union { __nv_bfloat16 b[4]; uint2 u; } hb, lb;
    float vv[4] = { v.x, v.y, v.z, v.w };
#pragma unroll
    for (int u = 0; u < 4; u++) {
        __nv_bfloat16 h = __float2bfloat16(vv[u]);
        hb.b[u] = h;
        lb.b[u] = __float2bfloat16(vv[u] - __bfloat162float(h));
    }
    ((uint2*)hi)[i] = hb.u;
    ((uint2*)lo)[i] = lb.u;
}

__global__ void tsplit_kernel(const float* __restrict__ in,
                              __nv_bfloat16* __restrict__ hi,
                              __nv_bfloat16* __restrict__ lo,
                              int K, int N, long outEStride, int ldOut, int colOffE) {
    __shared__ float t[32][33];
    int e = blockIdx.z;
    int n0 = blockIdx.x * 32, k0 = blockIdx.y * 32;
    const float* src = in + (long)e * K * N;
    int tx = threadIdx.x, ty = threadIdx.y;
#pragma unroll
    for (int i = 0; i < 32; i += 8)
        t[ty + i][tx] = src[(long)(k0 + ty + i) * N + n0 + tx];
    __syncthreads();
    long obase = (long)e * outEStride + (long)e * colOffE;
#pragma unroll
    for (int i = 0; i < 32; i += 8) {
        float v = t[tx][ty + i];
        __nv_bfloat16 h = __float2bfloat16(v);
        long o = obase + (long)(n0 + ty + i) * ldOut + k0 + tx;
        hi[o] = h;
        lo[o] = __float2bfloat16(v - __bfloat162float(h));
    }
}

// ===================== mma.sync bf16x3 GEMM (single-sync pipeline) ==========
// Tile 128x128, BK=32 per chunk; 128B rows: [0,64)=hi k, [64,128)=lo k.
// 3-stage ring, prefetch depth 2, ONE __syncthreads per chunk.
#define STAGES 3
#define STAGE_BYTES 32768
#define DSMEM_BYTES (STAGES * STAGE_BYTES)

template<bool GELU, bool GATHER, bool EXPERT>
__global__ __launch_bounds__(256, 2)
void mma_gemm(const __nv_bfloat16* __restrict__ Ahi_,
              const __nv_bfloat16* __restrict__ Alo_,
              const __nv_bfloat16* __restrict__ Bhi_,
              const __nv_bfloat16* __restrict__ Blo_,
              const float* __restrict__ bias_,
              const float* __restrict__ bias2,
              __nv_bfloat16* __restrict__ Chi_,
              __nv_bfloat16* __restrict__ Clo_,
              float* __restrict__ Cf_,
              int M, int K, int ldc, long wStride, int bStride, int colOffZ)
{
    int z = blockIdx.z;
    const __nv_bfloat16* Bhi = Bhi_ + (long)z * wStride;
    const __nv_bfloat16* Blo = Blo_ + (long)z * wStride;
    const float* bias = bias_ + (long)z * bStride;
    int colOff = colOffZ * z;
    const __nv_bfloat16* Ahi = Ahi_;
    const __nv_bfloat16* Alo = Alo_;
    __nv_bfloat16* Chi = Chi_;
    __nv_bfloat16* Clo = Clo_;
    float* Cf = Cf_;
    const int* list = nullptr;
    if (EXPERT) {
        M = g_counts[z];
        long b = g_base[z];
        if (GATHER) list = g_list + (long)z * T_TOK;
        else { Ahi += b * (long)K; Alo += b * (long)K; }
        if (GELU) { Chi += b * (long)ldc; Clo += b * (long)ldc; }
        else Cf += b * (long)ldc;
    }
    int rowBase = blockIdx.x * 128;
    if (rowBase >= M) return;
    int colBase = blockIdx.y * 128;

    extern __shared__ char smem[];
    uint32_t sbase = smem_u32(smem);

    int tid = threadIdx.x;
    int wid = tid >> 5, lane = tid & 31;
    int warpM = wid & 3, warpN = wid >> 2;

    // loader metadata: 4 16B units each for A and B per stage
    uint32_t swoff[4]; int aRow[4], bRow[4], kel[4], aBytes[4]; bool hiSel[4];
#pragma unroll
    for (int i = 0; i < 4; i++) {
        int id = tid + i * 256;
        int r = id >> 3;
        int c = id & 7;
        swoff[i] = SW128((uint32_t)(r * 128 + c * 16));
        kel[i] = (c & 3) * 8;
        hiSel[i] = c < 4;
        int gR = rowBase + r;
        bool ok = gR < M;
        aBytes[i] = ok ? 16 : 0;
        aRow[i] = GATHER ? (ok ? list[gR] : 0) : (ok ? gR : 0);
        bRow[i] = colBase + r;
    }

    const int NC = K >> 5;

    auto issue = [&](int ci) {
        uint32_t sA = sbase + (ci % STAGES) * STAGE_BYTES;
        uint32_t sB = sA + 16384;
        int kbase = ci << 5;
#pragma unroll
        for (int i = 0; i < 4; i++) {
            const __nv_bfloat16* as = (hiSel[i] ? Ahi : Alo) + (long)aRow[i] * K + kbase + kel[i];
            cp_async16(sA + swoff[i], as, aBytes[i]);
            const __nv_bfloat16* bs = (hiSel[i] ? Bhi : Blo) + (long)bRow[i] * K + kbase + kel[i];
            cp_async16(sB + swoff[i], bs, 16);
        }
        CP_COMMIT();
    };

    float acc[2][8][4];
#pragma unroll
    for (int mi = 0; mi < 2; mi++)
#pragma unroll
        for (int nj = 0; nj < 8; nj++)
#pragma unroll
            for (int u = 0; u < 4; u++) acc[mi][nj][u] = 0.f;

    int lrow = lane & 15;
    int lc16 = (lane >> 4) * 16;

    // Precompute swizzled base offsets (XOR-composable: SW128(x^d)=SW128(x)^d
    // for d in {32,64,96} since x's low 7 bits only carry bit 4).
    uint32_t swA[2], swB[4];
#pragma unroll
    for (int mi = 0; mi < 2; mi++)
        swA[mi] = SW128((uint32_t)((warpM * 32 + mi * 16 + lrow) * 128 + lc16));
#pragma unroll
    for (int g = 0; g < 4; g++)
        swB[g] = SW128((uint32_t)((warpN * 64 + g * 16 + lrow) * 128 + lc16));

    issue(0); issue(1);
    for (int ci = 0; ci < NC; ci++) {
        CP_WAIT(1);
        __syncthreads();
        if (ci + 2 < NC) issue(ci + 2);
        else CP_COMMIT();                 // keep group count invariant
        uint32_t sA = sbase + (ci % STAGES) * STAGE_BYTES;
        uint32_t sB = sA + 16384;
#pragma unroll
        for (int ks = 0; ks < 2; ks++) {
            uint32_t koff = ks * 32;
            uint32_t ah[2][4], al[2][4];
#pragma unroll
            for (int mi = 0; mi < 2; mi++) {
                ldsm4(ah[mi], sA + (swA[mi] ^ koff));
                ldsm4(al[mi], sA + (swA[mi] ^ (koff + 64)));
            }
#pragma unroll
            for (int g = 0; g < 4; g++) {
                uint32_t bh[4], bl[4];
                ldsm4(bh, sB + (swB[g] ^ koff));
                ldsm4(bl, sB + (swB[g] ^ (koff + 64)));
#pragma unroll
                for (int mi = 0; mi < 2; mi++) {
                    mma16816(acc[mi][2 * g + 0], ah[mi], bh[0], bh[2]);
                    mma16816(acc[mi][2 * g + 1], ah[mi], bh[1], bh[3]);
                    mma16816(acc[mi][2 * g + 0], al[mi], bh[0], bh[2]);
                    mma16816(acc[mi][2 * g + 1], al[mi], bh[1], bh[3]);
                    mma16816(acc[mi][2 * g + 0], ah[mi], bl[0], bl[2]);
                    mma16816(acc[mi][2 * g + 1], ah[mi], bl[1], bl[3]);
                }
            }
        }
    }

    // ---------------- epilogue ----------------
    __syncthreads();    // last stage reads done before CTA may exit/reuse smem
    int rw0 = rowBase + warpM * 32 + (lane >> 2);
    int cw0 = colBase + warpN * 64 + (lane & 3) * 2;
#pragma unroll
    for (int mi = 0; mi < 2; mi++) {
#pragma unroll
        for (int nj = 0; nj < 8; nj++) {
            int col = cw0 + nj * 8;
            float b0 = bias[col], b1 = bias[col + 1];
            if (bias2) { b0 += bias2[col]; b1 += bias2[col + 1]; }
#pragma unroll
            for (int h = 0; h < 2; h++) {
                int row = rw0 + mi * 16 + h * 8;
                if (row < M) {
                    float v0 = acc[mi][nj][2 * h + 0] + b0;
                    float v1 = acc[mi][nj][2 * h + 1] + b1;
                    long off = (long)row * ldc + colOff + col;
                    if (GELU) {
                        float g0 = 0.5f * v0 * (1.0f + erff(v0 * 0.70710678118654752f));
                        float g1 = 0.5f * v1 * (1.0f + erff(v1 * 0.70710678118654752f));
                        float h0 = __bfloat162float(__float2bfloat16(g0));
                        float h1 = __bfloat162float(__float2bfloat16(g1));
                        *(uint32_t*)(Chi + off) = pack_bf16(g0, g1);
                        *(uint32_t*)(Clo + off) = pack_bf16(g0 - h0, g1 - h1);
                    } else {
                        float2 v; v.x = v0; v.y = v1;
                        *(float2*)(Cf + off) = v;
                    }
                }
            }
        }
    }
}

// ===================== launch =====================
static void* symAddr(const void* sym) { void* p; cudaGetSymbolAddress(&p, sym); return p; }

extern "C" void kernel_launch(void* const* d_in, const int* in_sizes, int n_in,
                              void* d_out, int out_size)
{
    const float* x   = (const float*)d_in[0];
    const float* sw1 = (const float*)d_in[1];
    const float* sb1 = (const float*)d_in[2];
    const float* sw2 = (const float*)d_in[3];
    const float* sb2 = (const float*)d_in[4];
    const float* ew1 = (const float*)d_in[5];
    const float* eb1 = (const float*)d_in[6];
    const float* ew2 = (const float*)d_in[7];
    const float* eb2 = (const float*)d_in[8];
    const float* rw  = (const float*)d_in[9];
    const float* rb  = (const float*)d_in[10];
    float* out = (float*)d_out;

    __nv_bfloat16* x_hi   = (__nv_bfloat16*)symAddr(g_x_hi);
    __nv_bfloat16* x_lo   = (__nv_bfloat16*)symAddr(g_x_lo);
    __nv_bfloat16* sw1t_h = (__nv_bfloat16*)symAddr(g_sw1t_hi);
    __nv_bfloat16* sw1t_l = (__nv_bfloat16*)symAddr(g_sw1t_lo);
    __nv_bfloat16* ew1t_h = (__nv_bfloat16*)symAddr(g_ew1t_hi);
    __nv_bfloat16* ew1t_l = (__nv_bfloat16*)symAddr(g_ew1t_lo);
    __nv_bfloat16* sw2t_h = (__nv_bfloat16*)symAddr(g_sw2t_hi);
    __nv_bfloat16* sw2t_l = (__nv_bfloat16*)symAddr(g_sw2t_lo);
    __nv_bfloat16* ew2t_h = (__nv_bfloat16*)symAddr(g_ew2t_hi);
    __nv_bfloat16* ew2t_l = (__nv_bfloat16*)symAddr(g_ew2t_lo);
    __nv_bfloat16* hids_h = (__nv_bfloat16*)symAddr(g_hids_hi);
    __nv_bfloat16* hids_l = (__nv_bfloat16*)symAddr(g_hids_lo);
    __nv_bfloat16* hidr_h = (__nv_bfloat16*)symAddr(g_hidr_hi);
    __nv_bfloat16* hidr_l = (__nv_bfloat16*)symAddr(g_hidr_lo);
    float* rout = (float*)symAddr(g_rout);

    cudaFuncSetAttribute(mma_gemm<true, false, false>, cudaFuncAttributeMaxDynamicSharedMemorySize, DSMEM_BYTES);
    cudaFuncSetAttribute(mma_gemm<true, true,  true>,  cudaFuncAttributeMaxDynamicSharedMemorySize, DSMEM_BYTES);
    cudaFuncSetAttribute(mma_gemm<false, false, false>, cudaFuncAttributeMaxDynamicSharedMemorySize, DSMEM_BYTES);
    cudaFuncSetAttribute(mma_gemm<false, false, true>, cudaFuncAttributeMaxDynamicSharedMemorySize, DSMEM_BYTES);

    // Launch order arranged so kernel #6 (ncu -s 5 -c 1) is the routed GEMM1.
    zero_kernel<<<1, 32>>>();                                               // 1
    router_kernel<<<T_TOK / 4, 128>>>(x, rw, rb);                           // 2
    base_kernel<<<1, 32>>>();                                               // 3
    split_kernel<<<(T_TOK * H_DIM / 4 + 255) / 256, 256>>>(x, x_hi, x_lo, T_TOK * H_DIM / 4); // 4
    tsplit_kernel<<<dim3(F_DIM / 32, H_DIM / 32, E_NUM), dim3(32, 8)>>>(    // 5
        ew1, ew1t_h, ew1t_l, H_DIM, F_DIM, (long)F_DIM * H_DIM, H_DIM, 0);

    // 6: routed GEMM1 (PROFILED)
    mma_gemm<true, true, true><<<dim3(T_TOK / 128, F_DIM / 128, E_NUM), 256, DSMEM_BYTES>>>(
        x_hi, x_lo, ew1t_h, ew1t_l, eb1, nullptr, hidr_h, hidr_l, nullptr,
        0, H_DIM, F_DIM, (long)F_DIM * H_DIM, F_DIM, 0);

    tsplit_kernel<<<dim3(F_DIM / 32, H_DIM / 32, 2), dim3(32, 8)>>>(
        sw1, sw1t_h, sw1t_l, H_DIM, F_DIM, (long)F_DIM * H_DIM, H_DIM, 0);

    mma_gemm<true, false, false><<<dim3(T_TOK / 128, F_DIM / 128, 2), 256, DSMEM_BYTES>>>(
        x_hi, x_lo, sw1t_h, sw1t_l, sb1, nullptr, hids_h, hids_l, nullptr,
        T_TOK, H_DIM, F2, (long)F_DIM * H_DIM, F_DIM, F_DIM);

    tsplit_kernel<<<dim3(H_DIM / 32, F_DIM / 32, 2), dim3(32, 8)>>>(
        sw2, sw2t_h, sw2t_l, F_DIM, H_DIM, 0, F2, F_DIM);

    mma_gemm<false, false, false><<<dim3(T_TOK / 128, H_DIM / 128, 1), 256, DSMEM_BYTES>>>(
        hids_h, hids_l, sw2t_h, sw2t_l, sb2, sb2 + H_DIM, nullptr, nullptr, out,
        T_TOK, F2, H_DIM, 0, 0, 0);

    tsplit_kernel<<<dim3(H_DIM / 32, F_DIM / 32, E_NUM), dim3(32, 8)>>>(
        ew2, ew2t_h, ew2t_l, F_DIM, H_DIM, (long)H_DIM * F_DIM, F_DIM, 0);

    mma_gemm<false, false, true><<<dim3(T_TOK / 128, H_DIM / 128, E_NUM), 256, DSMEM_BYTES>>>(
        hidr_h, hidr_l, ew2t_h, ew2t_l, eb2, nullptr, nullptr, nullptr, rout,
        0, F_DIM, H_DIM, (long)H_DIM * F_DIM, H_DIM, 0);

    combine_kernel<<<T_TOK, 256>>>(out);
}

// round 6
// speedup vs baseline: 1.0181x; 1.0181x over previous
#include <cuda_runtime.h>
#include <cuda_bf16.h>
#include <cstdint>
#include <math.h>

#define T_TOK 4096
#define H_DIM 1024
#define F_DIM 2048
#define E_NUM 8
#define F2    (2 * F_DIM)

// ===================== helpers =====================
__device__ __forceinline__ uint32_t smem_u32(const void* p) {
    uint32_t a;
    asm("{ .reg .u64 t; cvta.to.shared.u64 t, %1; cvt.u32.u64 %0, t; }" : "=r"(a) : "l"(p));
    return a;
}
#define SW128(off) ((off) ^ (((off) >> 3) & 0x70))

__device__ __forceinline__ void cp_async16(uint32_t dst, const void* src, int srcBytes) {
    asm volatile("cp.async.cg.shared.global [%0], [%1], 16, %2;"
                 :: "r"(dst), "l"(src), "r"(srcBytes) : "memory");
}
#define CP_COMMIT() asm volatile("cp.async.commit_group;" ::: "memory")
#define CP_WAIT(n)  asm volatile("cp.async.wait_group %0;" :: "n"(n) : "memory")

__device__ __forceinline__ void ldsm4(uint32_t* r, uint32_t addr) {
    asm volatile("ldmatrix.sync.aligned.m8n8.x4.shared.b16 {%0,%1,%2,%3}, [%4];"
                 : "=r"(r[0]), "=r"(r[1]), "=r"(r[2]), "=r"(r[3]) : "r"(addr));
}

__device__ __forceinline__ void mma16816(float* d, const uint32_t* a, uint32_t b0, uint32_t b1) {
    asm volatile("mma.sync.aligned.m16n8k16.row.col.f32.bf16.bf16.f32 "
                 "{%0,%1,%2,%3}, {%4,%5,%6,%7}, {%8,%9}, {%0,%1,%2,%3};"
                 : "+f"(d[0]), "+f"(d[1]), "+f"(d[2]), "+f"(d[3])
                 : "r"(a[0]), "r"(a[1]), "r"(a[2]), "r"(a[3]), "r"(b0), "r"(b1));
}

__device__ __forceinline__ uint32_t pack_bf16(float x, float y) {
    __nv_bfloat162 t;
    t.x = __float2bfloat16(x);
    t.y = __float2bfloat16(y);
    return *(uint32_t*)&t;
}

// ===================== scratch (device globals; no allocs) =====================
__device__ __nv_bfloat16 g_x_hi [(size_t)T_TOK * H_DIM];
__device__ __nv_bfloat16 g_x_lo [(size_t)T_TOK * H_DIM];
__device__ __nv_bfloat16 g_sw1t_hi[(size_t)2 * F_DIM * H_DIM];
__device__ __nv_bfloat16 g_sw1t_lo[(size_t)2 * F_DIM * H_DIM];
__device__ __nv_bfloat16 g_ew1t_hi[(size_t)E_NUM * F_DIM * H_DIM];
__device__ __nv_bfloat16 g_ew1t_lo[(size_t)E_NUM * F_DIM * H_DIM];
__device__ __nv_bfloat16 g_sw2t_hi[(size_t)H_DIM * F2];
__device__ __nv_bfloat16 g_sw2t_lo[(size_t)H_DIM * F2];
__device__ __nv_bfloat16 g_ew2t_hi[(size_t)E_NUM * H_DIM * F_DIM];
__device__ __nv_bfloat16 g_ew2t_lo[(size_t)E_NUM * H_DIM * F_DIM];
__device__ __nv_bfloat16 g_hids_hi[(size_t)T_TOK * F2];
__device__ __nv_bfloat16 g_hids_lo[(size_t)T_TOK * F2];
__device__ __nv_bfloat16 g_hidr_hi[(size_t)2 * T_TOK * F_DIM];
__device__ __nv_bfloat16 g_hidr_lo[(size_t)2 * T_TOK * F_DIM];
__device__ float g_rout[(size_t)2 * T_TOK * H_DIM];
__device__ int g_counts[E_NUM];
__device__ int g_base[E_NUM];
__device__ int g_list[E_NUM * T_TOK];
__device__ int g_tok_e[2 * T_TOK];
__device__ int g_tok_slot[2 * T_TOK];

// ===================== small kernels =====================
__global__ void zero_kernel() {
    if (threadIdx.x < E_NUM) g_counts[threadIdx.x] = 0;
}

__global__ void router_kernel(const float* __restrict__ x,
                              const float* __restrict__ rw,
                              const float* __restrict__ rb) {
    int warp = (blockIdx.x * blockDim.x + threadIdx.x) >> 5;
    int lane = threadIdx.x & 31;
    if (warp >= T_TOK) return;
    const float* xp = x + (long)warp * H_DIM;
    float acc[E_NUM];
#pragma unroll
    for (int e = 0; e < E_NUM; e++) acc[e] = 0.f;
    for (int h = lane; h < H_DIM; h += 32) {
        float xv = xp[h];
        const float* w = rw + (long)h * E_NUM;
#pragma unroll
        for (int e = 0; e < E_NUM; e++) acc[e] = fmaf(xv, w[e], acc[e]);
    }
#pragma unroll
    for (int e = 0; e < E_NUM; e++)
#pragma unroll
        for (int off = 16; off; off >>= 1)
            acc[e] += __shfl_xor_sync(0xFFFFFFFFu, acc[e], off);
    if (lane == 0) {
        float lg[E_NUM];
#pragma unroll
        for (int e = 0; e < E_NUM; e++) lg[e] = acc[e] + rb[e];
        int e0 = 0;
#pragma unroll
        for (int e = 1; e < E_NUM; e++) if (lg[e] > lg[e0]) e0 = e;
        int e1 = -1;
#pragma unroll
        for (int e = 0; e < E_NUM; e++) {
            if (e == e0) continue;
            if (e1 < 0 || lg[e] > lg[e1]) e1 = e;
        }
        int sel[2] = { e0, e1 };
        int t = warp;
#pragma unroll
        for (int k = 0; k < 2; k++) {
            int e = sel[k];
            int slot = atomicAdd(&g_counts[e], 1);
            g_list[e * T_TOK + slot] = t;
            g_tok_e[2 * t + k] = e;
            g_tok_slot[2 * t + k] = slot;
        }
    }
}

__global__ void base_kernel() {
    if (threadIdx.x == 0) {
        int s = 0;
#pragma unroll
        for (int e = 0; e < E_NUM; e++) { g_base[e] = s; s += g_counts[e]; }
    }
}

__global__ void combine_kernel(float* __restrict__ out) {
    int t = blockIdx.x;
    int e0 = g_tok_e[2 * t], e1 = g_tok_e[2 * t + 1];
    long r0 = (long)g_base[e0] + g_tok_slot[2 * t];
    long r1 = (long)g_base[e1] + g_tok_slot[2 * t + 1];
    const float4* p0 = (const float4*)g_rout + r0 * (H_DIM / 4);
    const float4* p1 = (const float4*)g_rout + r1 * (H_DIM / 4);
    float4* op = (float4*)out + (long)t * (H_DIM / 4);
    int i = threadIdx.x;
    float4 o = op[i], a = p0[i], b = p1[i];
    o.x += a.x + b.x; o.y += a.y + b.y; o.z += a.z + b.z; o.w += a.w + b.w;
    op[i] = o;
}

// ===================== converters =====================
__global__ void split_kernel(const float* __restrict__ in,
                             __nv_bfloat16* __restrict__ hi,
                             __nv_bfloat16* __restrict__ lo, int n4) {
    int i = blockIdx.x * blockDim.x + threadIdx.x;
    if (i >= n4) return;
    float4 v = ((const float4*)in)[i];
    union { __nv_bfloat16 b[4]; uint2 u; } hb, lb;
    float vv[4] = { v.x, v.y, v.z, v.w };
#pragma unroll
    for (int u = 0; u < 4; u++) {
        __nv_bfloat16 h = __float2bfloat16(vv[u]);
        hb.b[u] = h;
        lb.b[u] = __float2bfloat16(vv[u] - __bfloat162float(h));
    }
    ((uint2*)hi)[i] = hb.u;
    ((uint2*)lo)[i] = lb.u;
}

// GEMM1 weights: [H][F] per slice -> K-major [F][H] hi/lo. z<8: ew1[z]; z>=8: sw1[z-8]
__global__ void tsplitG1(const float* __restrict__ sw1, const float* __restrict__ ew1) {
    __shared__ float t[32][33];
    int z = blockIdx.z;
    const float* src;
    __nv_bfloat16 *hi, *lo;
    if (z < E_NUM) {
        src = ew1 + (size_t)z * H_DIM * F_DIM;
        hi = g_ew1t_hi + (size_t)z * F_DIM * H_DIM;
        lo = g_ew1t_lo + (size_t)z * F_DIM * H_DIM;
    } else {
        int n = z - E_NUM;
        src = sw1 + (size_t)n * H_DIM * F_DIM;
        hi = g_sw1t_hi + (size_t)n * F_DIM * H_DIM;
        lo = g_sw1t_lo + (size_t)n * F_DIM * H_DIM;
    }
    int n0 = blockIdx.x * 32, k0 = blockIdx.y * 32;
    int tx = threadIdx.x, ty = threadIdx.y;
#pragma unroll
    for (int i = 0; i < 32; i += 8)
        t[ty + i][tx] = src[(long)(k0 + ty + i) * F_DIM + n0 + tx];
    __syncthreads();
#pragma unroll
    for (int i = 0; i < 32; i += 8) {
        float v = t[tx][ty + i];
        __nv_bfloat16 h = __float2bfloat16(v);
        long o = (long)(n0 + ty + i) * H_DIM + k0 + tx;
        hi[o] = h;
        lo[o] = __float2bfloat16(v - __bfloat162float(h));
    }
}

// GEMM2 weights: [F][H] per slice -> K-major rows of N=H. z<8: ew2[z] (ld F);
// z>=8: sw2[z-8] into concatenated ld F2 at col offset n*F.
__global__ void tsplitG2(const float* __restrict__ sw2, const float* __restrict__ ew2) {
    __shared__ float t[32][33];
    int z = blockIdx.z;
    const float* src;
    __nv_bfloat16 *hi, *lo;
    long obase; int ld;
    if (z < E_NUM) {
        src = ew2 + (size_t)z * F_DIM * H_DIM;
        hi = g_ew2t_hi; lo = g_ew2t_lo;
        obase = (size_t)z * H_DIM * F_DIM; ld = F_DIM;
    } else {
        int n = z - E_NUM;
        src = sw2 + (size_t)n * F_DIM * H_DIM;
        hi = g_sw2t_hi; lo = g_sw2t_lo;
        obase = (long)n * F_DIM; ld = F2;
    }
    int n0 = blockIdx.x * 32, k0 = blockIdx.y * 32;
    int tx = threadIdx.x, ty = threadIdx.y;
#pragma unroll
    for (int i = 0; i < 32; i += 8)
        t[ty + i][tx] = src[(long)(k0 + ty + i) * H_DIM + n0 + tx];
    __syncthreads();
#pragma unroll
    for (int i = 0; i < 32; i += 8) {
        float v = t[tx][ty + i];
        __nv_bfloat16 h = __float2bfloat16(v);
        long o = obase + (long)(n0 + ty + i) * ld + k0 + tx;
        hi[o] = h;
        lo[o] = __float2bfloat16(v - __bfloat162float(h));
    }
}

// ===================== GEMM core: CTA 128x64, 256 thr, warp 32x32 ==========
// A [M,K] hi/lo K-major (opt. gathered); B [N,K] hi/lo K-major.
// Per BK=32 chunk, 128B rows hold [hi k0..31 | lo k0..31].
// Stage = A 16KB + B 8KB = 24KB; 4 stages, prefetch depth 3.
#define STAGE_BYTES 24576
#define DSMEM_BYTES (4 * STAGE_BYTES)

template<bool GELU>
__device__ __forceinline__ void gemm_core(
    const __nv_bfloat16* __restrict__ Ahi, const __nv_bfloat16* __restrict__ Alo,
    const __nv_bfloat16* __restrict__ Bhi, const __nv_bfloat16* __restrict__ Blo,
    const float* __restrict__ bias, const float* __restrict__ bias2,
    __nv_bfloat16* Chi, __nv_bfloat16* Clo, float* Cf,
    int M, int K, int ldc, int colOff, const int* list, int rowBase)
{
    int colBase = blockIdx.y * 64;
    extern __shared__ char smem[];
    uint32_t sbase = smem_u32(smem);
    int tid = threadIdx.x;
    int wid = tid >> 5, lane = tid & 31;
    int warpM = wid & 3, warpN = wid >> 2;   // 4 x 2 warps

    // loader: 6 x 16B units/thread; units 0..1023 -> A, 1024..1535 -> B
    uint32_t swoff[6]; int row[6], kel[6], nbytes[6]; bool isA[6], hiSel[6];
#pragma unroll
    for (int i = 0; i < 6; i++) {
        int id = tid + i * 256;
        isA[i] = id < 1024;
        int u = isA[i] ? id : (id - 1024);
        int r = u >> 3, c = u & 7;
        swoff[i] = SW128((uint32_t)(r * 128 + c * 16)) + (isA[i] ? 0u : 16384u);
        kel[i] = (c & 3) * 8;
        hiSel[i] = c < 4;
        if (isA[i]) {
            int gR = rowBase + r;
            bool ok = gR < M;
            nbytes[i] = ok ? 16 : 0;
            row[i] = list ? (ok ? list[gR] : 0) : (ok ? gR : 0);
        } else {
            nbytes[i] = 16;
            row[i] = colBase + r;
        }
    }

    const int NC = K >> 5;
    auto issue = [&](int ci) {
        uint32_t st = sbase + (ci & 3) * STAGE_BYTES;
        int kbase = ci << 5;
#pragma unroll
        for (int i = 0; i < 6; i++) {
            const __nv_bfloat16* p = isA[i] ? (hiSel[i] ? Ahi : Alo)
                                            : (hiSel[i] ? Bhi : Blo);
            cp_async16(st + swoff[i], p + (long)row[i] * K + kbase + kel[i], nbytes[i]);
        }
        CP_COMMIT();
    };

    float acc[2][4][4];
#pragma unroll
    for (int mi = 0; mi < 2; mi++)
#pragma unroll
        for (int nj = 0; nj < 4; nj++)
#pragma unroll
            for (int u = 0; u < 4; u++) acc[mi][nj][u] = 0.f;

    int lrow = lane & 15;
    int lc16 = (lane >> 4) * 16;
    uint32_t swA[2], swB[2];
#pragma unroll
    for (int mi = 0; mi < 2; mi++)
        swA[mi] = SW128((uint32_t)((warpM * 32 + mi * 16 + lrow) * 128 + lc16));
#pragma unroll
    for (int g = 0; g < 2; g++)
        swB[g] = SW128((uint32_t)((warpN * 32 + g * 16 + lrow) * 128 + lc16)) + 16384u;

    issue(0); issue(1); issue(2);
    for (int ci = 0; ci < NC; ci++) {
        CP_WAIT(2);
        __syncthreads();
        if (ci + 3 < NC) issue(ci + 3);
        else CP_COMMIT();
        uint32_t st = sbase + (ci & 3) * STAGE_BYTES;
#pragma unroll
        for (int ks = 0; ks < 2; ks++) {
            uint32_t koff = ks * 32;
            uint32_t ah[2][4], al[2][4];
#pragma unroll
            for (int mi = 0; mi < 2; mi++) {
                ldsm4(ah[mi], st + (swA[mi] ^ koff));
                ldsm4(al[mi], st + (swA[mi] ^ (koff + 64)));
            }
#pragma unroll
            for (int g = 0; g < 2; g++) {
                uint32_t bh[4], bl[4];
                ldsm4(bh, st + (swB[g] ^ koff));
                ldsm4(bl, st + (swB[g] ^ (koff + 64)));
#pragma unroll
                for (int mi = 0; mi < 2; mi++) {
                    mma16816(acc[mi][2 * g + 0], ah[mi], bh[0], bh[2]);
                    mma16816(acc[mi][2 * g + 1], ah[mi], bh[1], bh[3]);
                    mma16816(acc[mi][2 * g + 0], al[mi], bh[0], bh[2]);
                    mma16816(acc[mi][2 * g + 1], al[mi], bh[1], bh[3]);
                    mma16816(acc[mi][2 * g + 0], ah[mi], bl[0], bl[2]);
                    mma16816(acc[mi][2 * g + 1], ah[mi], bl[1], bl[3]);
                }
            }
        }
    }

    // epilogue
    int rw0 = rowBase + warpM * 32 + (lane >> 2);
    int cw0 = colBase + warpN * 32 + (lane & 3) * 2;
#pragma unroll
    for (int mi = 0; mi < 2; mi++) {
#pragma unroll
        for (int nj = 0; nj < 4; nj++) {
            int col = cw0 + nj * 8;
            float b0 = bias[col], b1 = bias[col + 1];
            if (bias2) { b0 += bias2[col]; b1 += bias2[col + 1]; }
#pragma unroll
            for (int h = 0; h < 2; h++) {
                int row_ = rw0 + mi * 16 + h * 8;
                if (row_ < M) {
                    float v0 = acc[mi][nj][2 * h + 0] + b0;
                    float v1 = acc[mi][nj][2 * h + 1] + b1;
                    long off = (long)row_ * ldc + colOff + col;
                    if (GELU) {
                        float g0 = 0.5f * v0 * (1.0f + erff(v0 * 0.70710678118654752f));
                        float g1 = 0.5f * v1 * (1.0f + erff(v1 * 0.70710678118654752f));
                        float h0 = __bfloat162float(__float2bfloat16(g0));
                        float h1 = __bfloat162float(__float2bfloat16(g1));
                        *(uint32_t*)(Chi + off) = pack_bf16(g0, g1);
                        *(uint32_t*)(Clo + off) = pack_bf16(g0 - h0, g1 - h1);
                    } else {
                        float2 v; v.x = v0; v.y = v1;
                        *(float2*)(Cf + off) = v;
                    }
                }
            }
        }
    }
}

// GEMM1 merged: z<8 routed expert z (gather); z>=8 shared n=z-8.
__global__ __launch_bounds__(256, 2)
void moe_gemm1(const __nv_bfloat16* __restrict__ x_hi,
               const __nv_bfloat16* __restrict__ x_lo,
               const float* __restrict__ sb1, const float* __restrict__ eb1)
{
    int z = blockIdx.z;
    int M, ldc, colOff;
    const int* list;
    const __nv_bfloat16 *Bh, *Bl;
    const float* bias;
    __nv_bfloat16 *Ch, *Cl;
    if (z < E_NUM) {
        M = g_counts[z];
        list = g_list + (long)z * T_TOK;
        Bh = g_ew1t_hi + (size_t)z * F_DIM * H_DIM;
        Bl = g_ew1t_lo + (size_t)z * F_DIM * H_DIM;
        bias = eb1 + z * F_DIM;
        long b = g_base[z];
        Ch = g_hidr_hi + b * (long)F_DIM;
        Cl = g_hidr_lo + b * (long)F_DIM;
        ldc = F_DIM; colOff = 0;
    } else {
        int n = z - E_NUM;
        M = T_TOK;
        list = nullptr;
        Bh = g_sw1t_hi + (size_t)n * F_DIM * H_DIM;
        Bl = g_sw1t_lo + (size_t)n * F_DIM * H_DIM;
        bias = sb1 + n * F_DIM;
        Ch = g_hids_hi; Cl = g_hids_lo;
        ldc = F2; colOff = n * F_DIM;
    }
    int rowBase = blockIdx.x * 128;
    if (rowBase >= M) return;
    gemm_core<true>(x_hi, x_lo, Bh, Bl, bias, nullptr,
                    Ch, Cl, nullptr, M, H_DIM, ldc, colOff, list, rowBase);
}

// GEMM2 merged: z<8 routed expert z; z==8 shared (K=F2, writes out).
__global__ __launch_bounds__(256, 2)
void moe_gemm2(const float* __restrict__ sb2, const float* __restrict__ eb2,
               float* __restrict__ out)
{
    int z = blockIdx.z;
    int M, K;
    const __nv_bfloat16 *Ah, *Al, *Bh, *Bl;
    const float *bias, *bias2;
    float* Cf;
    if (z < E_NUM) {
        M = g_counts[z];
        long b = g_base[z];
        Ah = g_hidr_hi + b * (long)F_DIM;
        Al = g_hidr_lo + b * (long)F_DIM;
        K = F_DIM;
        Bh = g_ew2t_hi + (size_t)z * H_DIM * F_DIM;
        Bl = g_ew2t_lo + (size_t)z * H_DIM * F_DIM;
        bias = eb2 + z * H_DIM; bias2 = nullptr;
        Cf = g_rout + b * (long)H_DIM;
    } else {
        M = T_TOK;
        Ah = g_hids_hi; Al = g_hids_lo;
        K = F2;
        Bh = g_sw2t_hi; Bl = g_sw2t_lo;
        bias = sb2; bias2 = sb2 + H_DIM;
        Cf = out;
    }
    int rowBase = blockIdx.x * 128;
    if (rowBase >= M) return;
    gemm_core<false>(Ah, Al, Bh, Bl, bias, bias2,
                     nullptr, nullptr, Cf, M, K, H_DIM, 0, nullptr, rowBase);
}

// ===================== launch =====================
static void* symAddr(const void* sym) { void* p; cudaGetSymbolAddress(&p, sym); return p; }

extern "C" void kernel_launch(void* const* d_in, const int* in_sizes, int n_in,
                              void* d_out, int out_size)
{
    const float* x   = (const float*)d_in[0];
    const float* sw1 = (const float*)d_in[1];
    const float* sb1 = (const float*)d_in[2];
    const float* sw2 = (const float*)d_in[3];
    const float* sb2 = (const float*)d_in[4];
    const float* ew1 = (const float*)d_in[5];
    const float* eb1 = (const float*)d_in[6];
    const float* ew2 = (const float*)d_in[7];
    const float* eb2 = (const float*)d_in[8];
    const float* rw  = (const float*)d_in[9];
    const float* rb  = (const float*)d_in[10];
    float* out = (float*)d_out;

    __nv_bfloat16* x_hi = (__nv_bfloat16*)symAddr(g_x_hi);
    __nv_bfloat16* x_lo = (__nv_bfloat16*)symAddr(g_x_lo);

    cudaFuncSetAttribute(moe_gemm1, cudaFuncAttributeMaxDynamicSharedMemorySize, DSMEM_BYTES);
    cudaFuncSetAttribute(moe_gemm2, cudaFuncAttributeMaxDynamicSharedMemorySize, DSMEM_BYTES);

    zero_kernel<<<1, 32>>>();                                                   // 1
    router_kernel<<<T_TOK / 4, 128>>>(x, rw, rb);                               // 2
    base_kernel<<<1, 32>>>();                                                   // 3
    split_kernel<<<(T_TOK * H_DIM / 4 + 255) / 256, 256>>>(x, x_hi, x_lo,       // 4
                                                           T_TOK * H_DIM / 4);
    tsplitG1<<<dim3(F_DIM / 32, H_DIM / 32, E_NUM + 2), dim3(32, 8)>>>(sw1, ew1); // 5

    // 6 (PROFILED): merged GEMM1
    moe_gemm1<<<dim3(T_TOK / 128, F_DIM / 64, E_NUM + 2), 256, DSMEM_BYTES>>>(
        x_hi, x_lo, sb1, eb1);

    tsplitG2<<<dim3(H_DIM / 32, F_DIM / 32, E_NUM + 2), dim3(32, 8)>>>(sw2, ew2); // 7

    // 8: merged GEMM2
    moe_gemm2<<<dim3(T_TOK / 128, H_DIM / 64, E_NUM + 1), 256, DSMEM_BYTES>>>(
        sb2, eb2, out);

    combine_kernel<<<T_TOK, 256>>>(out);                                        // 9
}